// round 1
// baseline (speedup 1.0000x reference)
#include <cuda_runtime.h>
#include <cuda_bf16.h>

// LipsNet fused kernel.
// Per sample b:
//   z1 = W1 x + b1 ; h1 = relu(z1) ; r1 = z1>0
//   z2 = W2 h1 + b2; h2 = relu(z2) ; r2 = z2>0
//   f  = W3 h2 + b3
//   J  = W3 D2 W2 D1 W1   (D = diag of relu masks)
//   ||J||_F^2 computed as:
//     Stage A: U = (W3 cols masked by r2) @ W2          [64 x 256]
//     Stage B: V = (U  cols masked by r1) @ W1          [64 x 256]; ||J||^2 = sum V^2
//   out = tanh(softplus(k) * f / (||J|| + 1e-4))
//
// Block = 256 threads, one sample per block. Heavy stages use packed f32x2 FMA.

#define DIN  256
#define HID  256
#define DOUT 64
#define BATCH 8192
#define PITCH 68   // floats per row of the 256x64 broadcast buffer (16B aligned rows)

struct SM {
    float buf[256 * PITCH];  // stage A: W3^T [i][o]; stage B: U^T [j][o]
    float sx[DIN];
    float h1[HID];
    float h2[HID];
    float sf[DOUT];
    int   act1[HID];
    int   act2[HID];
    int   cnt1, cnt2;
    float red[8];
    float jn2;
};

__device__ __forceinline__ unsigned long long pack2(float x, float y) {
    unsigned long long r;
    asm("mov.b64 %0, {%1, %2};" : "=l"(r) : "f"(x), "f"(y));
    return r;
}
__device__ __forceinline__ void unpack2(unsigned long long v, float& x, float& y) {
    asm("mov.b64 {%0, %1}, %2;" : "=f"(x), "=f"(y) : "l"(v));
}
__device__ __forceinline__ void ffma2(unsigned long long& d, unsigned long long a, unsigned long long b) {
    // packed f32x2 fused multiply-add (sm_100+)
    asm("fma.rn.f32x2 %0, %1, %2, %0;" : "+l"(d) : "l"(a), "l"(b));
}

__global__ __launch_bounds__(256, 2) void lipsnet_kernel(
    const float* __restrict__ X,
    const float* __restrict__ W1, const float* __restrict__ B1,
    const float* __restrict__ W2, const float* __restrict__ B2,
    const float* __restrict__ W3, const float* __restrict__ B3,
    const float* __restrict__ Kp,
    float* __restrict__ out)
{
    extern __shared__ char smraw[];
    SM* s = reinterpret_cast<SM*>(smraw);

    const int b    = blockIdx.x;
    const int t    = threadIdx.x;
    const int lane = t & 31;
    const int wid  = t >> 5;

    // ---- load x, init counters, transpose W3 into buf (buf[i*PITCH+o] = W3[o,i]) ----
    s->sx[t] = X[b * DIN + t];
    if (t == 0) { s->cnt1 = 0; s->cnt2 = 0; }
    #pragma unroll
    for (int n = t; n < DOUT * HID; n += 256) {
        int o = n >> 8;          // 0..63
        int i = n & 255;         // 0..255
        s->buf[i * PITCH + o] = W3[n];
    }
    __syncthreads();

    // ---- forward z1 -> h1 (warp w computes hidden units w*32..w*32+31) ----
    {
        const int hbase = wid * 32;
        #pragma unroll 4
        for (int hh = 0; hh < 32; ++hh) {
            const int h = hbase + hh;
            const float* wr = W1 + h * DIN;
            float a = 0.f;
            #pragma unroll
            for (int d = 0; d < DIN; d += 32)
                a = fmaf(__ldg(wr + d + lane), s->sx[d + lane], a);
            #pragma unroll
            for (int off = 16; off; off >>= 1)
                a += __shfl_xor_sync(0xffffffffu, a, off);
            if (lane == 0) {
                a += B1[h];
                s->h1[h] = a > 0.f ? a : 0.f;
            }
        }
    }
    __syncthreads();

    if (s->h1[t] > 0.f) s->act1[atomicAdd(&s->cnt1, 1)] = t;

    // ---- forward z2 -> h2 ----
    {
        const int hbase = wid * 32;
        #pragma unroll 4
        for (int hh = 0; hh < 32; ++hh) {
            const int h = hbase + hh;
            const float* wr = W2 + h * HID;
            float a = 0.f;
            #pragma unroll
            for (int d = 0; d < HID; d += 32)
                a = fmaf(__ldg(wr + d + lane), s->h1[d + lane], a);
            #pragma unroll
            for (int off = 16; off; off >>= 1)
                a += __shfl_xor_sync(0xffffffffu, a, off);
            if (lane == 0) {
                a += B2[h];
                s->h2[h] = a > 0.f ? a : 0.f;
            }
        }
    }
    __syncthreads();

    if (s->h2[t] > 0.f) s->act2[atomicAdd(&s->cnt2, 1)] = t;

    // ---- forward f = W3 h2 + b3 (warp w computes outputs w*8..w*8+7) ----
    {
        const int obase = wid * 8;
        #pragma unroll
        for (int oo = 0; oo < 8; ++oo) {
            const int o = obase + oo;
            const float* wr = W3 + o * HID;
            float a = 0.f;
            #pragma unroll
            for (int d = 0; d < HID; d += 32)
                a = fmaf(__ldg(wr + d + lane), s->h2[d + lane], a);
            #pragma unroll
            for (int off = 16; off; off >>= 1)
                a += __shfl_xor_sync(0xffffffffu, a, off);
            if (lane == 0) s->sf[o] = a + B3[o];
        }
    }
    __syncthreads();

    // ---- Stage A: U[o, t] = sum_{i in act2} W3[o,i] * W2[i,t] ----
    unsigned long long acc[32];
    #pragma unroll
    for (int q = 0; q < 32; ++q) acc[q] = 0ull;

    const int n2 = s->cnt2;
    for (int ii = 0; ii < n2; ++ii) {
        const int i = s->act2[ii];
        const float w = __ldg(&W2[(i << 8) + t]);
        const unsigned long long ww = pack2(w, w);
        const ulonglong2* row = reinterpret_cast<const ulonglong2*>(&s->buf[i * PITCH]);
        #pragma unroll
        for (int q = 0; q < 16; ++q) {
            ulonglong2 v = row[q];          // LDS.128 broadcast: 4 W3^T values (2 f32x2 pairs)
            ffma2(acc[2 * q],     v.x, ww);
            ffma2(acc[2 * q + 1], v.y, ww);
        }
    }
    __syncthreads();   // everyone done reading buf as W3^T

    // store U transposed: buf[t*PITCH + 2p .. ] = acc pairs (thread t = column j of U)
    {
        unsigned long long* dst = reinterpret_cast<unsigned long long*>(&s->buf[t * PITCH]);
        #pragma unroll
        for (int q = 0; q < 32; ++q) dst[q] = acc[q];
    }
    __syncthreads();

    // ---- Stage B: V[o, t] = sum_{j in act1} U[o,j] * W1[j,t] ; ss = sum_o V[o,t]^2 ----
    unsigned long long vacc[32];
    #pragma unroll
    for (int q = 0; q < 32; ++q) vacc[q] = 0ull;

    const int n1 = s->cnt1;
    for (int ii = 0; ii < n1; ++ii) {
        const int j = s->act1[ii];
        const float w = __ldg(&W1[(j << 8) + t]);
        const unsigned long long ww = pack2(w, w);
        const ulonglong2* row = reinterpret_cast<const ulonglong2*>(&s->buf[j * PITCH]);
        #pragma unroll
        for (int q = 0; q < 16; ++q) {
            ulonglong2 v = row[q];
            ffma2(vacc[2 * q],     v.x, ww);
            ffma2(vacc[2 * q + 1], v.y, ww);
        }
    }

    float ss = 0.f;
    #pragma unroll
    for (int q = 0; q < 32; ++q) {
        float lo, hi;
        unpack2(vacc[q], lo, hi);
        ss = fmaf(lo, lo, ss);
        ss = fmaf(hi, hi, ss);
    }
    #pragma unroll
    for (int off = 16; off; off >>= 1)
        ss += __shfl_xor_sync(0xffffffffu, ss, off);
    if (lane == 0) s->red[wid] = ss;
    __syncthreads();
    if (t == 0) {
        float a = 0.f;
        #pragma unroll
        for (int w = 0; w < 8; ++w) a += s->red[w];
        s->jn2 = a;
    }
    __syncthreads();

    // ---- epilogue ----
    if (t < DOUT) {
        const float kk = __ldg(Kp);
        const float sp = (kk > 20.f) ? kk : log1pf(expf(kk));  // softplus
        const float denom = sqrtf(s->jn2) + 1e-4f;
        out[b * DOUT + t] = tanhf(sp * s->sf[t] / denom);
    }
}

extern "C" void kernel_launch(void* const* d_in, const int* in_sizes, int n_in,
                              void* d_out, int out_size)
{
    const float* X  = (const float*)d_in[0];
    const float* W1 = (const float*)d_in[1];
    const float* B1 = (const float*)d_in[2];
    const float* W2 = (const float*)d_in[3];
    const float* B2 = (const float*)d_in[4];
    const float* W3 = (const float*)d_in[5];
    const float* B3 = (const float*)d_in[6];
    const float* Kp = (const float*)d_in[7];
    float* out = (float*)d_out;

    const int smem = (int)sizeof(SM);
    cudaFuncSetAttribute(lipsnet_kernel, cudaFuncAttributeMaxDynamicSharedMemorySize, smem);
    lipsnet_kernel<<<BATCH, 256, smem>>>(X, W1, B1, W2, B2, W3, B3, Kp, out);
}

// round 3
// speedup vs baseline: 3.2753x; 3.2753x over previous
#include <cuda_runtime.h>
#include <cuda_fp16.h>
#include <cstdint>

#define B_TOT 8192
#define DIN   256
#define HID   256
#define DOUT  64

// ---------------- device scratch (static, no allocations) ----------------
// k-interleaved f16 copies (per 16-col block, storage order
// [0,1,8,9,2,3,10,11,4,5,12,13,6,7,14,15]) so mma fragments load as LDS.64.
__device__ __align__(16) __half g_W2h[HID * HID];   // [n][k=i interleaved]  B of GEMM1
__device__ __align__(16) __half g_W1h[DIN * HID];   // [d][k=j interleaved]  B of GEMM2
__device__ __align__(16) __half g_W3h[DOUT * HID];  // [o][k=i interleaved]  A source
__device__ __align__(16) float  g_f[B_TOT * DOUT];
__device__ unsigned g_r1[B_TOT * 8];
__device__ unsigned g_r2[B_TOT * 8];

// ---------------- helpers ----------------
__device__ __forceinline__ uint32_t smem_u32(const void* p) {
    uint32_t a;
    asm("{ .reg .u64 t; cvta.to.shared.u64 t, %1; cvt.u32.u64 %0, t; }" : "=r"(a) : "l"(p));
    return a;
}
__device__ __forceinline__ void lds64(uint32_t& x, uint32_t& y, uint32_t addr) {
    asm volatile("ld.shared.v2.b32 {%0,%1}, [%2];" : "=r"(x), "=r"(y) : "r"(addr));
}
__device__ __forceinline__ void mma16816(float c[4], uint32_t a0, uint32_t a1,
                                         uint32_t a2, uint32_t a3,
                                         uint32_t b0, uint32_t b1) {
    asm volatile(
        "mma.sync.aligned.m16n8k16.row.col.f32.f16.f16.f32 "
        "{%0,%1,%2,%3}, {%4,%5,%6,%7}, {%8,%9}, {%0,%1,%2,%3};"
        : "+f"(c[0]), "+f"(c[1]), "+f"(c[2]), "+f"(c[3])
        : "r"(a0), "r"(a1), "r"(a2), "r"(a3), "r"(b0), "r"(b1));
}

// interleave order: storage slot s (0..15) holds column col(s)
__device__ __host__ __forceinline__ int ilv_col(int s) {
    return ((s >> 2) * 2) + (s & 1) + (((s >> 1) & 1) * 8);
}

// =====================================================================
// prep: build f16 k-interleaved B/A operand copies
// =====================================================================
__global__ void prep_kernel(const float* __restrict__ W1, const float* __restrict__ W2,
                            const float* __restrict__ W3) {
    const int bz = blockIdx.x, t = threadIdx.x;
    if (bz < 256) {                       // g_W2h[n][kk] = W2[k][n]
        int idx = bz * 256 + t;
        int n = idx >> 8, kk = idx & 255, kb = kk >> 4, s = kk & 15;
        int c = ilv_col(s);
        g_W2h[idx] = __float2half_rn(W2[(kb * 16 + c) * 256 + n]);
    } else if (bz < 512) {                // g_W1h[d][kk] = W1[k][d]
        int idx = (bz - 256) * 256 + t;
        int d = idx >> 8, kk = idx & 255, kb = kk >> 4, s = kk & 15;
        int c = ilv_col(s);
        g_W1h[idx] = __float2half_rn(W1[(kb * 16 + c) * 256 + d]);
    } else {                              // g_W3h[o][kk] = W3[o][k]
        int idx = (bz - 512) * 256 + t;
        int o = idx >> 8, kk = idx & 255, kb = kk >> 4, s = kk & 15;
        int c = ilv_col(s);
        g_W3h[idx] = __float2half_rn(W3[o * 256 + kb * 16 + c]);
    }
}

// =====================================================================
// forward MLP (exact fp32) + ReLU bitmasks, 16 samples / block
// =====================================================================
__global__ __launch_bounds__(256) void fwd_kernel(
    const float* __restrict__ X,
    const float* __restrict__ W1, const float* __restrict__ B1,
    const float* __restrict__ W2, const float* __restrict__ B2,
    const float* __restrict__ W3, const float* __restrict__ B3)
{
    __shared__ float bufA[16][256];  // x, later h2
    __shared__ float bufB[16][256];  // h1
    const int t = threadIdx.x, lane = t & 31, wid = t >> 5;
    const int s0 = blockIdx.x * 16;

    {
        const float4* src = (const float4*)(X + (size_t)s0 * 256);
        float4* dst = (float4*)&bufA[0][0];
        for (int i = t; i < 16 * 64; i += 256) dst[i] = __ldg(src + i);
    }
    __syncthreads();

    float acc[16];
    // layer 1
    {
        #pragma unroll
        for (int s = 0; s < 16; ++s) acc[s] = 0.f;
        const float4* wr = (const float4*)(W1 + t * 256);
        for (int j = 0; j < 64; ++j) {
            float4 w = __ldg(wr + j);
            #pragma unroll
            for (int s = 0; s < 16; ++s) {
                float4 xv = ((const float4*)bufA[s])[j];
                acc[s] = fmaf(w.x, xv.x, acc[s]);
                acc[s] = fmaf(w.y, xv.y, acc[s]);
                acc[s] = fmaf(w.z, xv.z, acc[s]);
                acc[s] = fmaf(w.w, xv.w, acc[s]);
            }
        }
        const float b = __ldg(B1 + t);
        #pragma unroll
        for (int s = 0; s < 16; ++s) {
            float z = acc[s] + b;
            unsigned m = __ballot_sync(0xffffffffu, z > 0.f);
            if (lane == 0) g_r1[(size_t)(s0 + s) * 8 + wid] = m;
            bufB[s][t] = z > 0.f ? z : 0.f;
        }
    }
    __syncthreads();
    // layer 2
    {
        #pragma unroll
        for (int s = 0; s < 16; ++s) acc[s] = 0.f;
        const float4* wr = (const float4*)(W2 + t * 256);
        for (int j = 0; j < 64; ++j) {
            float4 w = __ldg(wr + j);
            #pragma unroll
            for (int s = 0; s < 16; ++s) {
                float4 xv = ((const float4*)bufB[s])[j];
                acc[s] = fmaf(w.x, xv.x, acc[s]);
                acc[s] = fmaf(w.y, xv.y, acc[s]);
                acc[s] = fmaf(w.z, xv.z, acc[s]);
                acc[s] = fmaf(w.w, xv.w, acc[s]);
            }
        }
        const float b = __ldg(B2 + t);
        #pragma unroll
        for (int s = 0; s < 16; ++s) {
            float z = acc[s] + b;
            unsigned m = __ballot_sync(0xffffffffu, z > 0.f);
            if (lane == 0) g_r2[(size_t)(s0 + s) * 8 + wid] = m;
            bufA[s][t] = z > 0.f ? z : 0.f;
        }
    }
    __syncthreads();
    // layer 3
    {
        const int o = t & 63, sg = t >> 6;
        float a4[4] = {0.f, 0.f, 0.f, 0.f};
        const float4* wr = (const float4*)(W3 + o * 256);
        for (int j = 0; j < 64; ++j) {
            float4 w = __ldg(wr + j);
            #pragma unroll
            for (int q = 0; q < 4; ++q) {
                float4 hv = ((const float4*)bufA[sg * 4 + q])[j];
                a4[q] = fmaf(w.x, hv.x, a4[q]);
                a4[q] = fmaf(w.y, hv.y, a4[q]);
                a4[q] = fmaf(w.z, hv.z, a4[q]);
                a4[q] = fmaf(w.w, hv.w, a4[q]);
            }
        }
        const float b = __ldg(B3 + o);
        #pragma unroll
        for (int q = 0; q < 4; ++q)
            g_f[(size_t)(s0 + sg * 4 + q) * 64 + o] = a4[q] + b;
    }
}

// =====================================================================
// jac kernel: 2 samples/CTA, two 128x256x256 f16 mma.sync GEMMs
// SMEM: AU buf 128 rows x 544B = 69632 ; B ring 2 x 24576 ; misc
// =====================================================================
#define AU_PITCH 544
#define B_PITCH  96
#define B_CHUNK  24576            // 256 rows * 96B per k32 chunk
#define SM_B     69632
#define SM_MISC  118784
#define SMEMJ    119040

__device__ __forceinline__ void cp_chunk(uint32_t dst, const __half* src, int c, int tid) {
    const int seg = tid & 3, n0 = tid >> 2;
    const char* gp = (const char*)src + (size_t)c * 64 + (size_t)seg * 16 + (size_t)n0 * 512;
    uint32_t d = dst + (uint32_t)n0 * B_PITCH + (uint32_t)seg * 16;
    #pragma unroll
    for (int p = 0; p < 4; ++p)
        asm volatile("cp.async.cg.shared.global [%0], [%1], 16;"
                     :: "r"(d + p * 64 * B_PITCH), "l"(gp + (size_t)p * 64 * 512) : "memory");
    asm volatile("cp.async.commit_group;" ::: "memory");
}

__device__ __forceinline__ void gemm256(uint32_t au, uint32_t bb0, const __half* Bsrc,
                                        float (&acc)[4][8][4], int M0, int N0,
                                        int g, int tig, int tid) {
    cp_chunk(bb0, Bsrc, 0, tid);
    cp_chunk(bb0 + B_CHUNK, Bsrc, 1, tid);
    const uint32_t abase = au + (uint32_t)(M0 + g) * AU_PITCH + (uint32_t)tig * 8;
    const uint32_t bcol  = (uint32_t)(N0 + g) * B_PITCH + (uint32_t)tig * 8;
    #pragma unroll 1
    for (int c = 0; c < 8; ++c) {
        if (c < 7) asm volatile("cp.async.wait_group 1;" ::: "memory");
        else       asm volatile("cp.async.wait_group 0;" ::: "memory");
        __syncthreads();
        const uint32_t bb = bb0 + (uint32_t)(c & 1) * B_CHUNK + bcol;
        #pragma unroll
        for (int kt2 = 0; kt2 < 2; ++kt2) {
            const int kt = c * 2 + kt2;
            uint32_t a[4][4];
            #pragma unroll
            for (int mt = 0; mt < 4; ++mt) {
                uint32_t ad = abase + (uint32_t)mt * (16 * AU_PITCH) + (uint32_t)kt * 32;
                lds64(a[mt][0], a[mt][2], ad);
                lds64(a[mt][1], a[mt][3], ad + 8 * AU_PITCH);
            }
            #pragma unroll
            for (int nt = 0; nt < 8; ++nt) {
                uint32_t b0, b1;
                lds64(b0, b1, bb + (uint32_t)nt * (8 * B_PITCH) + (uint32_t)kt2 * 32);
                #pragma unroll
                for (int mt = 0; mt < 4; ++mt)
                    mma16816(acc[mt][nt], a[mt][0], a[mt][1], a[mt][2], a[mt][3], b0, b1);
            }
        }
        __syncthreads();
        if (c + 2 < 8) cp_chunk(bb0 + (uint32_t)(c & 1) * B_CHUNK, Bsrc, c + 2, tid);
    }
}

__global__ __launch_bounds__(256, 1) void jac_kernel(const float* __restrict__ Kp,
                                                     float* __restrict__ out) {
    extern __shared__ char smem[];
    const uint32_t sb = smem_u32(smem);
    const int tid = threadIdx.x, lane = tid & 31, wid = tid >> 5;
    const int g = lane >> 2, tig = lane & 3;
    const int wm = wid & 1, wn = wid >> 1;
    const int M0 = wm * 64, N0 = wn * 64;
    const int s0 = blockIdx.x * 2;

    unsigned* r1s = (unsigned*)(smem + SM_MISC);        // 16 words (2 samples)
    unsigned* r2s = (unsigned*)(smem + SM_MISC + 64);   // 16 words
    float*    red = (float*)(smem + SM_MISC + 128);     // 8 floats

    if (tid < 16)      r1s[tid]      = g_r1[(size_t)s0 * 8 + tid];
    else if (tid < 32) r2s[tid - 16] = g_r2[(size_t)s0 * 8 + (tid - 16)];
    __syncthreads();

    // ---- load masked A = [W3 D2(s0) ; W3 D2(s0+1)] into AU (f16 interleaved) ----
    {
        const int m = tid >> 1, o = m & 63, samp = m >> 6;
        const uint4* src = (const uint4*)(g_W3h + o * 256);
        const unsigned* rw = r2s + samp * 8;
        #pragma unroll
        for (int qq = 0; qq < 16; ++qq) {
            const int q = (tid & 1) * 16 + qq;       // 16B chunk index 0..31
            uint4 v = __ldg(src + q);
            const int kb = q >> 1, h = q & 1;
            uint32_t* vv = (uint32_t*)&v;
            #pragma unroll
            for (int p = 0; p < 4; ++p) {
                const int c0 = kb * 16 + ((p & 1) * 8) + ((p >> 1) * 2) + h * 4;
                const unsigned bits = (rw[c0 >> 5] >> (c0 & 31)) & 3u;
                unsigned msk = ((bits & 1u) ? 0x0000FFFFu : 0u) |
                               ((bits & 2u) ? 0xFFFF0000u : 0u);
                vv[p] &= msk;
            }
            *(uint4*)(smem + m * AU_PITCH + q * 16) = v;
        }
    }

    float acc[4][8][4];
    #pragma unroll
    for (int mt = 0; mt < 4; ++mt)
        #pragma unroll
        for (int nt = 0; nt < 8; ++nt)
            #pragma unroll
            for (int q = 0; q < 4; ++q) acc[mt][nt][q] = 0.f;

    // ---- GEMM1: U = A @ W2h^T ----
    gemm256(sb, sb + SM_B, g_W2h, acc, M0, N0, g, tig, tid);

    __syncthreads();
    // ---- write U (masked by r1, f16, interleaved) into AU ----
    {
        const unsigned* rw = r1s + ((unsigned)M0 >> 6) * 8;   // sample = wm
        #pragma unroll
        for (int mt = 0; mt < 4; ++mt) {
            #pragma unroll
            for (int nt = 0; nt < 8; ++nt) {
                const int j = N0 + 8 * nt + 2 * tig;
                const unsigned bits = (rw[j >> 5] >> (j & 31)) & 3u;
                const int pos = ((j >> 1) & 3) * 4 + ((j >> 3) & 1) * 2;
                const uint32_t coff = (uint32_t)(j >> 4) * 32 + (uint32_t)pos * 2;
                #pragma unroll
                for (int half = 0; half < 2; ++half) {
                    const int row = M0 + 16 * mt + g + half * 8;
                    float v0 = acc[mt][nt][half * 2 + 0];
                    float v1 = acc[mt][nt][half * 2 + 1];
                    __half h0 = (bits & 1u) ? __float2half_rn(v0) : __ushort_as_half(0);
                    __half h1 = (bits & 2u) ? __float2half_rn(v1) : __ushort_as_half(0);
                    *(__half2*)(smem + row * AU_PITCH + coff) = __halves2half2(h0, h1);
                    acc[mt][nt][half * 2 + 0] = 0.f;
                    acc[mt][nt][half * 2 + 1] = 0.f;
                }
            }
        }
    }
    __syncthreads();

    // ---- GEMM2: V = U_masked @ W1h^T ----
    gemm256(sb, sb + SM_B, g_W1h, acc, M0, N0, g, tig, tid);

    // ---- ||J||^2 and output ----
    float ss = 0.f;
    #pragma unroll
    for (int mt = 0; mt < 4; ++mt)
        #pragma unroll
        for (int nt = 0; nt < 8; ++nt)
            #pragma unroll
            for (int q = 0; q < 4; ++q)
                ss = fmaf(acc[mt][nt][q], acc[mt][nt][q], ss);
    #pragma unroll
    for (int off = 16; off; off >>= 1)
        ss += __shfl_xor_sync(0xffffffffu, ss, off);
    if (lane == 0) red[wid] = ss;
    __syncthreads();

    if (tid < 128) {
        const int sloc = tid >> 6, o = tid & 63;
        const float jn2 = red[sloc] + red[sloc + 2] + red[sloc + 4] + red[sloc + 6];
        const float fv = g_f[(size_t)(s0 + sloc) * 64 + o];
        const float kk = __ldg(Kp);
        const float sp = (kk > 20.f) ? kk : log1pf(expf(kk));
        out[(size_t)(s0 + sloc) * 64 + o] = tanhf(sp * fv / (sqrtf(jn2) + 1e-4f));
    }
}

// =====================================================================
extern "C" void kernel_launch(void* const* d_in, const int* in_sizes, int n_in,
                              void* d_out, int out_size)
{
    const float* X  = (const float*)d_in[0];
    const float* W1 = (const float*)d_in[1];
    const float* B1 = (const float*)d_in[2];
    const float* W2 = (const float*)d_in[3];
    const float* B2 = (const float*)d_in[4];
    const float* W3 = (const float*)d_in[5];
    const float* B3 = (const float*)d_in[6];
    const float* Kp = (const float*)d_in[7];
    float* out = (float*)d_out;

    cudaFuncSetAttribute(jac_kernel, cudaFuncAttributeMaxDynamicSharedMemorySize, SMEMJ);

    prep_kernel<<<576, 256>>>(W1, W2, W3);
    fwd_kernel<<<B_TOT / 16, 256>>>(X, W1, B1, W2, B2, W3, B3);
    jac_kernel<<<B_TOT / 2, 256, SMEMJ>>>(Kp, out);
}

// round 4
// speedup vs baseline: 4.9060x; 1.4979x over previous
#include <cuda_runtime.h>
#include <cuda_fp16.h>
#include <cstdint>

#define B_TOT 8192

// ---------------- device scratch ----------------
__device__ __align__(16) __half g_W2f[256 * 256];  // plain W2, f16   (B of GEMM1, k-row-major)
__device__ __align__(16) __half g_W1f[256 * 256];  // plain W1, f16   (B of GEMM2)
__device__ __align__(16) __half g_W3T[256 * 64];   // W3^T, f16       (A of GEMM1: [k=i][o])
__device__ __align__(16) float  g_f[B_TOT * 64];
__device__ unsigned g_r1[B_TOT * 8];
__device__ unsigned g_r2[B_TOT * 8];

// ---------------- helpers ----------------
__device__ __forceinline__ uint32_t smem_u32(const void* p) {
    uint32_t a;
    asm("{ .reg .u64 t; cvta.to.shared.u64 t, %1; cvt.u32.u64 %0, t; }" : "=r"(a) : "l"(p));
    return a;
}
__device__ __forceinline__ void cp16(uint32_t dst, const void* src) {
    asm volatile("cp.async.cg.shared.global [%0], [%1], 16;" :: "r"(dst), "l"(src) : "memory");
}
#define CP_COMMIT() asm volatile("cp.async.commit_group;" ::: "memory")
__device__ __forceinline__ void ldm4t(uint32_t& r0, uint32_t& r1, uint32_t& r2, uint32_t& r3,
                                      uint32_t addr) {
    asm volatile("ldmatrix.sync.aligned.m8n8.x4.trans.shared.b16 {%0,%1,%2,%3}, [%4];"
                 : "=r"(r0), "=r"(r1), "=r"(r2), "=r"(r3) : "r"(addr));
}
__device__ __forceinline__ void mma16816(float c[4], uint32_t a0, uint32_t a1,
                                         uint32_t a2, uint32_t a3,
                                         uint32_t b0, uint32_t b1) {
    asm volatile(
        "mma.sync.aligned.m16n8k16.row.col.f32.f16.f16.f32 "
        "{%0,%1,%2,%3}, {%4,%5,%6,%7}, {%8,%9}, {%0,%1,%2,%3};"
        : "+f"(c[0]), "+f"(c[1]), "+f"(c[2]), "+f"(c[3])
        : "r"(a0), "r"(a1), "r"(a2), "r"(a3), "r"(b0), "r"(b1));
}

// =====================================================================
// prep: f16 copies (k-row-major everywhere)
// =====================================================================
__global__ void prep_kernel(const float* __restrict__ W1, const float* __restrict__ W2,
                            const float* __restrict__ W3) {
    int idx = blockIdx.x * 256 + threadIdx.x;
    if (idx < 65536) g_W2f[idx] = __float2half_rn(W2[idx]);
    else if (idx < 131072) g_W1f[idx - 65536] = __float2half_rn(W1[idx - 65536]);
    else {
        int l = idx - 131072;
        int i = l >> 6, o = l & 63;
        g_W3T[l] = __float2half_rn(W3[o * 256 + i]);
    }
}

// =====================================================================
// forward MLP (fp32 exact) + ReLU bitmasks, 16 samples / block
// =====================================================================
__global__ __launch_bounds__(256) void fwd_kernel(
    const float* __restrict__ X,
    const float* __restrict__ W1, const float* __restrict__ B1,
    const float* __restrict__ W2, const float* __restrict__ B2,
    const float* __restrict__ W3, const float* __restrict__ B3)
{
    __shared__ float bufA[16][256];
    __shared__ float bufB[16][256];
    const int t = threadIdx.x, lane = t & 31, wid = t >> 5;
    const int s0 = blockIdx.x * 16;

    {
        const float4* src = (const float4*)(X + (size_t)s0 * 256);
        float4* dst = (float4*)&bufA[0][0];
        for (int i = t; i < 16 * 64; i += 256) dst[i] = __ldg(src + i);
    }
    __syncthreads();

    float acc[16];
    {   // layer 1
        #pragma unroll
        for (int s = 0; s < 16; ++s) acc[s] = 0.f;
        const float4* wr = (const float4*)(W1 + t * 256);
        for (int j = 0; j < 64; ++j) {
            float4 w = __ldg(wr + j);
            #pragma unroll
            for (int s = 0; s < 16; ++s) {
                float4 xv = ((const float4*)bufA[s])[j];
                acc[s] = fmaf(w.x, xv.x, acc[s]); acc[s] = fmaf(w.y, xv.y, acc[s]);
                acc[s] = fmaf(w.z, xv.z, acc[s]); acc[s] = fmaf(w.w, xv.w, acc[s]);
            }
        }
        const float b = __ldg(B1 + t);
        #pragma unroll
        for (int s = 0; s < 16; ++s) {
            float z = acc[s] + b;
            unsigned m = __ballot_sync(0xffffffffu, z > 0.f);
            if (lane == 0) g_r1[(size_t)(s0 + s) * 8 + wid] = m;
            bufB[s][t] = z > 0.f ? z : 0.f;
        }
    }
    __syncthreads();
    {   // layer 2
        #pragma unroll
        for (int s = 0; s < 16; ++s) acc[s] = 0.f;
        const float4* wr = (const float4*)(W2 + t * 256);
        for (int j = 0; j < 64; ++j) {
            float4 w = __ldg(wr + j);
            #pragma unroll
            for (int s = 0; s < 16; ++s) {
                float4 xv = ((const float4*)bufB[s])[j];
                acc[s] = fmaf(w.x, xv.x, acc[s]); acc[s] = fmaf(w.y, xv.y, acc[s]);
                acc[s] = fmaf(w.z, xv.z, acc[s]); acc[s] = fmaf(w.w, xv.w, acc[s]);
            }
        }
        const float b = __ldg(B2 + t);
        #pragma unroll
        for (int s = 0; s < 16; ++s) {
            float z = acc[s] + b;
            unsigned m = __ballot_sync(0xffffffffu, z > 0.f);
            if (lane == 0) g_r2[(size_t)(s0 + s) * 8 + wid] = m;
            bufA[s][t] = z > 0.f ? z : 0.f;
        }
    }
    __syncthreads();
    {   // layer 3
        const int o = t & 63, sg = t >> 6;
        float a4[4] = {0.f, 0.f, 0.f, 0.f};
        const float4* wr = (const float4*)(W3 + o * 256);
        for (int j = 0; j < 64; ++j) {
            float4 w = __ldg(wr + j);
            #pragma unroll
            for (int q = 0; q < 4; ++q) {
                float4 hv = ((const float4*)bufA[sg * 4 + q])[j];
                a4[q] = fmaf(w.x, hv.x, a4[q]); a4[q] = fmaf(w.y, hv.y, a4[q]);
                a4[q] = fmaf(w.z, hv.z, a4[q]); a4[q] = fmaf(w.w, hv.w, a4[q]);
            }
        }
        const float b = __ldg(B3 + o);
        #pragma unroll
        for (int q = 0; q < 4; ++q)
            g_f[(size_t)(s0 + sg * 4 + q) * 64 + o] = a4[q] + b;
    }
}

// =====================================================================
// jac kernel: 1 sample/CTA, K-compacted f16 GEMMs via gathered rows
// A: [k<=256][64] pitch 144 ; B ring: 2 x (32 rows x pitch 528)
// =====================================================================
#define A_PITCH 144
#define B_PITCH 528
#define B_SLOT  16896
#define SM_B    36864u
#define SM_MISC 70656u
#define SMEMJ   72448

__device__ __forceinline__ void gatherB(uint32_t sb, int slot, const __half* W,
                                        const unsigned short* idx, int c, int tid) {
    const int r0 = tid >> 5, seg = tid & 31;
    const uint32_t dbase = sb + SM_B + (uint32_t)slot * B_SLOT + (uint32_t)seg * 16;
    #pragma unroll
    for (int p = 0; p < 4; ++p) {
        const int r = r0 + p * 8;
        cp16(dbase + (uint32_t)r * B_PITCH,
             (const char*)W + (size_t)idx[c * 32 + r] * 512 + (size_t)seg * 16);
    }
    CP_COMMIT();
}

__device__ __forceinline__ void chunk_mma(uint32_t a_addr, uint32_t b_addr,
                                          float (&acc)[2][8][4]) {
    #pragma unroll
    for (int ks = 0; ks < 2; ++ks) {
        uint32_t a[2][4];
        #pragma unroll
        for (int mt = 0; mt < 2; ++mt)
            ldm4t(a[mt][0], a[mt][1], a[mt][2], a[mt][3],
                  a_addr + (uint32_t)ks * (16 * A_PITCH) + (uint32_t)mt * 32);
        uint32_t b[4][4];
        #pragma unroll
        for (int ng = 0; ng < 4; ++ng)
            ldm4t(b[ng][0], b[ng][1], b[ng][2], b[ng][3],
                  b_addr + (uint32_t)ks * (16 * B_PITCH) + (uint32_t)ng * 32);
        #pragma unroll
        for (int mt = 0; mt < 2; ++mt)
            #pragma unroll
            for (int nt = 0; nt < 8; ++nt)
                mma16816(acc[mt][nt], a[mt][0], a[mt][1], a[mt][2], a[mt][3],
                         b[nt >> 1][(nt & 1) * 2], b[nt >> 1][(nt & 1) * 2 + 1]);
    }
}

__device__ __forceinline__ void run_gemm(uint32_t sb, const __half* W,
                                         const unsigned short* idx, int nch,
                                         uint32_t a_lane, uint32_t b_lane,
                                         float (&acc)[2][8][4], int tid) {
    gatherB(sb, 0, W, idx, 0, tid);
    if (nch > 1) gatherB(sb, 1, W, idx, 1, tid);
    for (int c = 0; c < nch; ++c) {
        if (c + 1 < nch) asm volatile("cp.async.wait_group 1;" ::: "memory");
        else             asm volatile("cp.async.wait_group 0;" ::: "memory");
        __syncthreads();
        chunk_mma(a_lane + (uint32_t)c * (32 * A_PITCH),
                  b_lane + (uint32_t)(c & 1) * B_SLOT, acc);
        __syncthreads();
        if (c + 2 < nch) gatherB(sb, c & 1, W, idx, c + 2, tid);
    }
}

__global__ __launch_bounds__(256, 2) void jac_kernel(const float* __restrict__ Kp,
                                                     float* __restrict__ out) {
    extern __shared__ char smem[];
    const uint32_t sb = smem_u32(smem);
    const int tid = threadIdx.x, lane = tid & 31, wid = tid >> 5;
    const int g = lane >> 2, tig = lane & 3;
    const int wm = wid & 1, wn = wid >> 1;
    const int s = blockIdx.x;

    unsigned* m2s = (unsigned*)(smem + SM_MISC);
    unsigned* m1s = m2s + 8;
    unsigned* p2s = m2s + 16;   // [9]
    unsigned* p1s = m2s + 25;   // [9]
    float*    red = (float*)(m2s + 34);
    unsigned short* idx2 = (unsigned short*)(smem + SM_MISC + 176);
    unsigned short* idx1 = idx2 + 256;
    unsigned short* pos1 = idx2 + 512;

    if (tid < 8)       m2s[tid]     = g_r2[(size_t)s * 8 + tid];
    else if (tid < 16) m1s[tid - 8] = g_r1[(size_t)s * 8 + (tid - 8)];
    __syncthreads();
    if (tid == 0)  { unsigned p = 0; for (int w = 0; w < 8; ++w) { p2s[w] = p; p += __popc(m2s[w]); } p2s[8] = p; }
    if (tid == 32) { unsigned p = 0; for (int w = 0; w < 8; ++w) { p1s[w] = p; p += __popc(m1s[w]); } p1s[8] = p; }
    __syncthreads();
    {
        const int j = tid, w = j >> 5, bi = j & 31;
        const unsigned below = (bi == 0) ? 0u : ((1u << bi) - 1u);
        if ((m2s[w] >> bi) & 1u)
            idx2[p2s[w] + __popc(m2s[w] & below)] = (unsigned short)j;
        if ((m1s[w] >> bi) & 1u) {
            unsigned p = p1s[w] + __popc(m1s[w] & below);
            idx1[p] = (unsigned short)j;
            pos1[j] = (unsigned short)p;
        }
    }
    __syncthreads();
    const int n2 = p2s[8], n1 = p1s[8];
    if (tid >= n2) idx2[tid] = 0;
    if (tid >= n1) idx1[tid] = 0;
    __syncthreads();
    int nch2 = (n2 + 31) >> 5; if (nch2 < 1) nch2 = 1;
    int nch1 = (n1 + 31) >> 5; if (nch1 < 1) nch1 = 1;

    // ---- A1 gather: rows = active i of W3T (128B rows) ----
    for (int i = tid; i < n2 * 8; i += 256) {
        const int r = i >> 3, seg = i & 7;
        cp16(sb + (uint32_t)r * A_PITCH + (uint32_t)seg * 16,
             (const char*)g_W3T + (size_t)idx2[r] * 128 + (size_t)seg * 16);
    }
    CP_COMMIT();
    {   // zero pad rows [n2, nch2*32)
        const int npad = nch2 * 32 - n2;
        for (int i = tid; i < npad * 9; i += 256) {
            const int r = n2 + i / 9, seg = i % 9;
            *(uint4*)(smem + r * A_PITCH + seg * 16) = make_uint4(0, 0, 0, 0);
        }
    }

    float acc[2][8][4];
    #pragma unroll
    for (int mt = 0; mt < 2; ++mt)
        #pragma unroll
        for (int nt = 0; nt < 8; ++nt)
            #pragma unroll
            for (int q = 0; q < 4; ++q) acc[mt][nt][q] = 0.f;

    const uint32_t a_lane = sb + (uint32_t)((lane & 7) + ((lane >> 4) & 1) * 8) * A_PITCH
                               + (uint32_t)((lane >> 3) & 1) * 16 + (uint32_t)wm * 64;
    const uint32_t b_lane = sb + SM_B
                               + (uint32_t)((lane & 7) + ((lane >> 3) & 1) * 8) * B_PITCH
                               + (uint32_t)((lane >> 4) & 1) * 16 + (uint32_t)wn * 128;

    // ---- GEMM1: U[64][256] ----
    run_gemm(sb, g_W2f, idx2, nch2, a_lane, b_lane, acc, tid);

    // ---- zero A2 pad rows + write U compacted (A2[pos(j)][o]) ----
    {
        const int npad = nch1 * 32 - n1;
        for (int i = tid; i < npad * 9; i += 256) {
            const int r = n1 + i / 9, seg = i % 9;
            *(uint4*)(smem + r * A_PITCH + seg * 16) = make_uint4(0, 0, 0, 0);
        }
    }
    #pragma unroll
    for (int mt = 0; mt < 2; ++mt)
        #pragma unroll
        for (int nt = 0; nt < 8; ++nt)
            #pragma unroll
            for (int q = 0; q < 4; ++q) {
                const int m = wm * 32 + mt * 16 + g + (q >> 1) * 8;
                const int j = wn * 64 + nt * 8 + 2 * tig + (q & 1);
                if ((m1s[j >> 5] >> (j & 31)) & 1u)
                    *(__half*)(smem + (uint32_t)pos1[j] * A_PITCH + (uint32_t)m * 2) =
                        __float2half_rn(acc[mt][nt][q]);
                acc[mt][nt][q] = 0.f;
            }
    __syncthreads();

    // ---- GEMM2: V[64][256] ----
    run_gemm(sb, g_W1f, idx1, nch1, a_lane, b_lane, acc, tid);

    // ---- ||J||^2 + output ----
    float ss = 0.f;
    #pragma unroll
    for (int mt = 0; mt < 2; ++mt)
        #pragma unroll
        for (int nt = 0; nt < 8; ++nt)
            #pragma unroll
            for (int q = 0; q < 4; ++q)
                ss = fmaf(acc[mt][nt][q], acc[mt][nt][q], ss);
    #pragma unroll
    for (int off = 16; off; off >>= 1)
        ss += __shfl_xor_sync(0xffffffffu, ss, off);
    if (lane == 0) red[wid] = ss;
    __syncthreads();

    if (tid < 64) {
        float jn2 = red[0] + red[1] + red[2] + red[3] +
                    red[4] + red[5] + red[6] + red[7];
        const float fv = g_f[(size_t)s * 64 + tid];
        const float kk = __ldg(Kp);
        const float sp = (kk > 20.f) ? kk : log1pf(expf(kk));
        out[(size_t)s * 64 + tid] = tanhf(sp * fv / (sqrtf(jn2) + 1e-4f));
    }
}

// =====================================================================
extern "C" void kernel_launch(void* const* d_in, const int* in_sizes, int n_in,
                              void* d_out, int out_size)
{
    const float* X  = (const float*)d_in[0];
    const float* W1 = (const float*)d_in[1];
    const float* B1 = (const float*)d_in[2];
    const float* W2 = (const float*)d_in[3];
    const float* B2 = (const float*)d_in[4];
    const float* W3 = (const float*)d_in[5];
    const float* B3 = (const float*)d_in[6];
    const float* Kp = (const float*)d_in[7];
    float* out = (float*)d_out;

    cudaFuncSetAttribute(jac_kernel, cudaFuncAttributeMaxDynamicSharedMemorySize, SMEMJ);

    prep_kernel<<<576, 256>>>(W1, W2, W3);
    fwd_kernel<<<B_TOT / 16, 256>>>(X, W1, B1, W2, B2, W3, B3);
    jac_kernel<<<B_TOT, 256, SMEMJ>>>(Kp, out);
}